// round 2
// baseline (speedup 1.0000x reference)
#include <cuda_runtime.h>
#include <cstdint>

// Problem constants (from reference)
#define NU 100000
#define NI 50000
#define NB 20000
#define DD 64
#define NN (NU + NI)
#define BQ 4096
#define NLAYER_SCALE (1.0f / 3.0f)

// Scratch (no runtime allocation allowed)
__device__ float g_feat0[(size_t)NN * DD];   // concat(users_feature, items_feature), later all_features
__device__ float g_f1[(size_t)NN * DD];      // layer-1 propagation
__device__ float g_f2[(size_t)NN * DD];      // layer-2 propagation
__device__ float g_bund[(size_t)NB * DD];    // bundle representations

// ---------------------------------------------------------------------------
// Edge-parallel SpMM: out[rows[e]] += vals[e] * x[cols[e]]
// 16 threads per edge, each handles one float4 (16B) via vector L2 reduction.
// ---------------------------------------------------------------------------
__global__ void spmm_edge16(const int* __restrict__ rows,
                            const int* __restrict__ cols,
                            const float* __restrict__ vals,
                            const float* __restrict__ x,
                            float* __restrict__ out,
                            int nE) {
    int t = blockIdx.x * blockDim.x + threadIdx.x;
    int e = t >> 4;
    if (e >= nE) return;
    int l = t & 15;

    int r = rows[e];
    int c = cols[e];
    float v = vals[e];

    const float4* xp = reinterpret_cast<const float4*>(x + (size_t)c * DD) + l;
    float4 xv = __ldg(xp);

    float4 o;
    o.x = xv.x * v; o.y = xv.y * v; o.z = xv.z * v; o.w = xv.w * v;

    float* dst = out + (size_t)r * DD + l * 4;
    asm volatile("red.global.add.v4.f32 [%0], {%1,%2,%3,%4};"
                 :: "l"(dst), "f"(o.x), "f"(o.y), "f"(o.z), "f"(o.w)
                 : "memory");
}

// ---------------------------------------------------------------------------
// all_features = (feat0 + f1 + f2) / 3, written in place into feat0
// ---------------------------------------------------------------------------
__global__ void combine3(float* __restrict__ f0,
                         const float* __restrict__ f1,
                         const float* __restrict__ f2,
                         int n4) {
    int i = blockIdx.x * blockDim.x + threadIdx.x;
    if (i >= n4) return;
    float4 a = reinterpret_cast<float4*>(f0)[i];
    float4 b = reinterpret_cast<const float4*>(f1)[i];
    float4 c = reinterpret_cast<const float4*>(f2)[i];
    float4 o;
    o.x = (a.x + b.x + c.x) * NLAYER_SCALE;
    o.y = (a.y + b.y + c.y) * NLAYER_SCALE;
    o.z = (a.z + b.z + c.z) * NLAYER_SCALE;
    o.w = (a.w + b.w + c.w) * NLAYER_SCALE;
    reinterpret_cast<float4*>(f0)[i] = o;
}

// ---------------------------------------------------------------------------
// BPR loss: one warp per query row.
// pred[k] = dot(user_emb, bundle_emb_k); loss = mean(softplus(-(pos - neg)))
// Accumulated into out[0] via atomics (out pre-zeroed). out[1] = c_loss = 0.
// ---------------------------------------------------------------------------
__global__ void bpr_loss_kernel(const int* __restrict__ users,
                                const int* __restrict__ bundles,
                                const float* __restrict__ feat,   // all_features (users part at offset 0)
                                const float* __restrict__ bund,
                                float* __restrict__ out) {
    int w = (blockIdx.x * blockDim.x + threadIdx.x) >> 5;
    int lane = threadIdx.x & 31;
    if (w >= BQ) return;

    int u  = users[w];
    int b0 = bundles[2 * w + 0];
    int b1 = bundles[2 * w + 1];

    float2 ue = reinterpret_cast<const float2*>(feat + (size_t)u  * DD)[lane];
    float2 e0 = reinterpret_cast<const float2*>(bund + (size_t)b0 * DD)[lane];
    float2 e1 = reinterpret_cast<const float2*>(bund + (size_t)b1 * DD)[lane];

    float d = ue.x * (e0.x - e1.x) + ue.y * (e0.y - e1.y);
    #pragma unroll
    for (int o = 16; o > 0; o >>= 1)
        d += __shfl_xor_sync(0xFFFFFFFFu, d, o);

    if (lane == 0) {
        float x = d;  // pos - neg
        // -log_sigmoid(x) = softplus(-x), numerically stable
        float sp = (x > 0.0f) ? log1pf(expf(-x)) : (-x + log1pf(expf(x)));
        atomicAdd(out, sp * (1.0f / BQ));
    }
}

// ---------------------------------------------------------------------------
// Launch
// ---------------------------------------------------------------------------
extern "C" void kernel_launch(void* const* d_in, const int* in_sizes, int n_in,
                              void* d_out, int out_size) {
    const float* users_feature = (const float*)d_in[0];
    const float* items_feature = (const float*)d_in[1];
    const float* prop_vals     = (const float*)d_in[2];
    const float* bi_vals       = (const float*)d_in[3];
    const int*   prop_rows     = (const int*)d_in[4];
    const int*   prop_cols     = (const int*)d_in[5];
    const int*   bi_rows       = (const int*)d_in[6];
    const int*   bi_cols       = (const int*)d_in[7];
    const int*   users         = (const int*)d_in[8];
    const int*   bundles       = (const int*)d_in[9];
    float*       out           = (float*)d_out;

    int nE_prop = in_sizes[4];  // 2 * E_UI = 4,000,000
    int nE_bi   = in_sizes[6];  // 600,000

    float *feat0, *f1, *f2, *bund;
    cudaGetSymbolAddress((void**)&feat0, g_feat0);
    cudaGetSymbolAddress((void**)&f1,    g_f1);
    cudaGetSymbolAddress((void**)&f2,    g_f2);
    cudaGetSymbolAddress((void**)&bund,  g_bund);

    // Stage 0: assemble feat0 = concat(users_feature, items_feature); zero scratch.
    cudaMemcpyAsync(feat0,                  users_feature, (size_t)NU * DD * sizeof(float),
                    cudaMemcpyDeviceToDevice, 0);
    cudaMemcpyAsync(feat0 + (size_t)NU * DD, items_feature, (size_t)NI * DD * sizeof(float),
                    cudaMemcpyDeviceToDevice, 0);
    cudaMemsetAsync(f1,   0, (size_t)NN * DD * sizeof(float), 0);
    cudaMemsetAsync(f2,   0, (size_t)NN * DD * sizeof(float), 0);
    cudaMemsetAsync(bund, 0, (size_t)NB * DD * sizeof(float), 0);
    cudaMemsetAsync(d_out, 0, (size_t)out_size * sizeof(float), 0);

    const int TPB = 256;

    // Layer 1: f1 = A @ feat0
    {
        long long threads = (long long)nE_prop * 16;
        int blocks = (int)((threads + TPB - 1) / TPB);
        spmm_edge16<<<blocks, TPB>>>(prop_rows, prop_cols, prop_vals, feat0, f1, nE_prop);
    }
    // Layer 2: f2 = A @ f1
    {
        long long threads = (long long)nE_prop * 16;
        int blocks = (int)((threads + TPB - 1) / TPB);
        spmm_edge16<<<blocks, TPB>>>(prop_rows, prop_cols, prop_vals, f1, f2, nE_prop);
    }
    // all_features = (feat0 + f1 + f2)/3  (in place into feat0)
    {
        int n4 = NN * DD / 4;
        int blocks = (n4 + TPB - 1) / TPB;
        combine3<<<blocks, TPB>>>(feat0, f1, f2, n4);
    }
    // Bundle aggregation: bund = Bi @ all_features[NU:]
    {
        long long threads = (long long)nE_bi * 16;
        int blocks = (int)((threads + TPB - 1) / TPB);
        spmm_edge16<<<blocks, TPB>>>(bi_rows, bi_cols, bi_vals, feat0 + (size_t)NU * DD, bund, nE_bi);
    }
    // BPR loss
    {
        int threads = BQ * 32;
        int blocks = (threads + TPB - 1) / TPB;
        bpr_loss_kernel<<<blocks, TPB>>>(users, bundles, feat0, bund, out);
    }
}

// round 4
// speedup vs baseline: 1.4771x; 1.4771x over previous
#include <cuda_runtime.h>
#include <cstdint>

// Problem constants (from reference)
#define NU 100000
#define NI 50000
#define NB 20000
#define DD 64
#define NN (NU + NI)
#define BQ 4096
#define NE_PROP_MAX 4000000
#define NE_BI_MAX   600000

#define SCAN_ELEMS 1024   // elements per scan block (256 threads x 4)
#define NBLK_PROP ((NN + SCAN_ELEMS - 1) / SCAN_ELEMS)   // 147
#define NBLK_BI   ((NB + SCAN_ELEMS - 1) / SCAN_ELEMS)   // 20

// ---- scratch (static; no runtime allocation) ----
__device__ float  g_f1[(size_t)NN * DD];       // layer-1 propagation
__device__ float  g_allfeat[(size_t)NN * DD];  // all_features (written by fused layer2)
__device__ float  g_bund[(size_t)NB * DD];     // bundle reps

__device__ int    g_deg[NN];
__device__ int    g_rs[NN + 1];                // prop CSR row_start
__device__ int    g_cur[NN];
__device__ int    g_bsums[NBLK_PROP];
__device__ float2 g_ecv[NE_PROP_MAX];          // packed (col,val) per edge

__device__ int    g_bdeg[NB];
__device__ int    g_brs[NB + 1];
__device__ int    g_bcur[NB];
__device__ int    g_bbsums[NBLK_BI];
__device__ float2 g_becv[NE_BI_MAX];

// ---------------------------------------------------------------------------
// degree histogram
// ---------------------------------------------------------------------------
__global__ void hist_kernel(const int* __restrict__ rows, int* __restrict__ deg, int nE) {
    int e = blockIdx.x * blockDim.x + threadIdx.x;
    if (e < nE) atomicAdd(&deg[rows[e]], 1);
}

// ---------------------------------------------------------------------------
// exclusive scan, 3-phase (block-local scan + block sums, scan sums, add)
// ---------------------------------------------------------------------------
__global__ void scan_local(const int* __restrict__ deg, int* __restrict__ excl,
                           int* __restrict__ bsums, int n) {
    __shared__ int sh[256];
    int tid = threadIdx.x;
    int base = blockIdx.x * SCAN_ELEMS + tid * 4;
    int v[4]; int s = 0;
    #pragma unroll
    for (int k = 0; k < 4; k++) {
        v[k] = (base + k < n) ? deg[base + k] : 0;
        s += v[k];
    }
    sh[tid] = s;
    __syncthreads();
    for (int off = 1; off < 256; off <<= 1) {
        int t = (tid >= off) ? sh[tid - off] : 0;
        __syncthreads();
        sh[tid] += t;
        __syncthreads();
    }
    if (tid == 255) bsums[blockIdx.x] = sh[255];
    int run = sh[tid] - s;     // exclusive within block
    #pragma unroll
    for (int k = 0; k < 4; k++) {
        if (base + k < n) excl[base + k] = run;
        run += v[k];
    }
}

__global__ void scan_bsums(int* __restrict__ bsums, int nb) {
    __shared__ int sh[256];
    int tid = threadIdx.x;
    int v = (tid < nb) ? bsums[tid] : 0;
    sh[tid] = v;
    __syncthreads();
    for (int off = 1; off < 256; off <<= 1) {
        int t = (tid >= off) ? sh[tid - off] : 0;
        __syncthreads();
        sh[tid] += t;
        __syncthreads();
    }
    if (tid < nb) bsums[tid] = sh[tid] - v;   // exclusive
}

__global__ void scan_add(int* __restrict__ excl, const int* __restrict__ bsums,
                         int n, int total) {
    int i = blockIdx.x * blockDim.x + threadIdx.x;
    if (i < n) excl[i] += bsums[i / SCAN_ELEMS];
    if (i == 0) excl[n] = total;
}

// ---------------------------------------------------------------------------
// CSR scatter-pack: ecv[pos] = (col, val)
// ---------------------------------------------------------------------------
__global__ void csr_scatter(const int* __restrict__ rows, const int* __restrict__ cols,
                            const float* __restrict__ vals,
                            const int* __restrict__ rs, int* __restrict__ cur,
                            float2* __restrict__ ecv, int nE) {
    int e = blockIdx.x * blockDim.x + threadIdx.x;
    if (e >= nE) return;
    int r = rows[e];
    int p = rs[r] + atomicAdd(&cur[r], 1);
    ecv[p] = make_float2(__int_as_float(cols[e]), vals[e]);
}

// ---------------------------------------------------------------------------
// Gather SpMM: warp per row, lane owns 2 dims. Input x is a virtual concat
// [xu ; xi] split at `split`. If COMBINE: out[row] = (f0[row]+f1[row]+acc)/3
// where f0 is virtual concat [f0u ; f0i] split at NU.
// ---------------------------------------------------------------------------
template<bool COMBINE>
__global__ void spmm_gather(const int* __restrict__ rs, const float2* __restrict__ ecv,
                            const float* __restrict__ xu, const float* __restrict__ xi,
                            int split,
                            float* __restrict__ out,
                            const float* __restrict__ f0u, const float* __restrict__ f0i,
                            const float* __restrict__ f1, int nrows) {
    int w = (blockIdx.x * blockDim.x + threadIdx.x) >> 5;
    int lane = threadIdx.x & 31;
    if (w >= nrows) return;

    int s = rs[w];
    int e = rs[w + 1];
    float accx = 0.f, accy = 0.f;

    for (int base = s; base < e; base += 32) {
        int idx = base + lane;
        float2 cv = make_float2(__int_as_float(0), 0.f);
        if (idx < e) cv = ecv[idx];
        int cnt = min(32, e - base);
        #pragma unroll 4
        for (int j = 0; j < cnt; ++j) {
            int c   = __shfl_sync(0xFFFFFFFFu, __float_as_int(cv.x), j);
            float v = __shfl_sync(0xFFFFFFFFu, cv.y, j);
            const float* xb;
            size_t off;
            if (c < split) { xb = xu; off = (size_t)c * DD; }
            else           { xb = xi; off = (size_t)(c - split) * DD; }
            float2 xv = reinterpret_cast<const float2*>(xb + off)[lane];
            accx = fmaf(v, xv.x, accx);
            accy = fmaf(v, xv.y, accy);
        }
    }

    if (COMBINE) {
        const float* f0 = (w < NU) ? (f0u + (size_t)w * DD)
                                   : (f0i + (size_t)(w - NU) * DD);
        float2 a = reinterpret_cast<const float2*>(f0)[lane];
        float2 b = reinterpret_cast<const float2*>(f1 + (size_t)w * DD)[lane];
        accx = (accx + a.x + b.x) * (1.0f / 3.0f);
        accy = (accy + a.y + b.y) * (1.0f / 3.0f);
    }
    reinterpret_cast<float2*>(out + (size_t)w * DD)[lane] = make_float2(accx, accy);
}

// ---------------------------------------------------------------------------
// BPR loss: one warp per query row.
// ---------------------------------------------------------------------------
__global__ void bpr_loss_kernel(const int* __restrict__ users,
                                const int* __restrict__ bundles,
                                const float* __restrict__ feat,
                                const float* __restrict__ bund,
                                float* __restrict__ out) {
    int w = (blockIdx.x * blockDim.x + threadIdx.x) >> 5;
    int lane = threadIdx.x & 31;
    if (w >= BQ) return;

    int u  = users[w];
    int b0 = bundles[2 * w + 0];
    int b1 = bundles[2 * w + 1];

    float2 ue = reinterpret_cast<const float2*>(feat + (size_t)u  * DD)[lane];
    float2 e0 = reinterpret_cast<const float2*>(bund + (size_t)b0 * DD)[lane];
    float2 e1 = reinterpret_cast<const float2*>(bund + (size_t)b1 * DD)[lane];

    float d = ue.x * (e0.x - e1.x) + ue.y * (e0.y - e1.y);
    #pragma unroll
    for (int o = 16; o > 0; o >>= 1)
        d += __shfl_xor_sync(0xFFFFFFFFu, d, o);

    if (lane == 0) {
        float x = d;
        float sp = (x > 0.0f) ? log1pf(expf(-x)) : (-x + log1pf(expf(x)));
        atomicAdd(out, sp * (1.0f / BQ));
    }
}

// ---------------------------------------------------------------------------
// Launch
// ---------------------------------------------------------------------------
extern "C" void kernel_launch(void* const* d_in, const int* in_sizes, int n_in,
                              void* d_out, int out_size) {
    const float* users_feature = (const float*)d_in[0];
    const float* items_feature = (const float*)d_in[1];
    const float* prop_vals     = (const float*)d_in[2];
    const float* bi_vals       = (const float*)d_in[3];
    const int*   prop_rows     = (const int*)d_in[4];
    const int*   prop_cols     = (const int*)d_in[5];
    const int*   bi_rows       = (const int*)d_in[6];
    const int*   bi_cols       = (const int*)d_in[7];
    const int*   users         = (const int*)d_in[8];
    const int*   bundles       = (const int*)d_in[9];
    float*       out           = (float*)d_out;

    int nE_prop = in_sizes[4];   // 4,000,000
    int nE_bi   = in_sizes[6];   // 600,000

    float *f1, *allfeat, *bund;
    int *deg, *rs, *cur, *bsums, *bdeg, *brs, *bcur, *bbsums;
    float2 *ecv, *becv;
    cudaGetSymbolAddress((void**)&f1,      g_f1);
    cudaGetSymbolAddress((void**)&allfeat, g_allfeat);
    cudaGetSymbolAddress((void**)&bund,    g_bund);
    cudaGetSymbolAddress((void**)&deg,     g_deg);
    cudaGetSymbolAddress((void**)&rs,      g_rs);
    cudaGetSymbolAddress((void**)&cur,     g_cur);
    cudaGetSymbolAddress((void**)&bsums,   g_bsums);
    cudaGetSymbolAddress((void**)&ecv,     g_ecv);
    cudaGetSymbolAddress((void**)&bdeg,    g_bdeg);
    cudaGetSymbolAddress((void**)&brs,     g_brs);
    cudaGetSymbolAddress((void**)&bcur,    g_bcur);
    cudaGetSymbolAddress((void**)&bbsums,  g_bbsums);
    cudaGetSymbolAddress((void**)&becv,    g_becv);

    const int TPB = 256;

    cudaMemsetAsync(deg,  0, NN * sizeof(int), 0);
    cudaMemsetAsync(cur,  0, NN * sizeof(int), 0);
    cudaMemsetAsync(bdeg, 0, NB * sizeof(int), 0);
    cudaMemsetAsync(bcur, 0, NB * sizeof(int), 0);
    cudaMemsetAsync(d_out, 0, (size_t)out_size * sizeof(float), 0);

    // ---- prop CSR build ----
    hist_kernel<<<(nE_prop + TPB - 1) / TPB, TPB>>>(prop_rows, deg, nE_prop);
    scan_local<<<NBLK_PROP, 256>>>(deg, rs, bsums, NN);
    scan_bsums<<<1, 256>>>(bsums, NBLK_PROP);
    scan_add<<<(NN + TPB - 1) / TPB, TPB>>>(rs, bsums, NN, nE_prop);
    csr_scatter<<<(nE_prop + TPB - 1) / TPB, TPB>>>(prop_rows, prop_cols, prop_vals,
                                                    rs, cur, ecv, nE_prop);

    // ---- layer 1: f1 = A @ [users_feature ; items_feature] ----
    {
        int blocks = (NN * 32 + TPB - 1) / TPB;
        spmm_gather<false><<<blocks, TPB>>>(rs, ecv, users_feature, items_feature, NU,
                                            f1, nullptr, nullptr, nullptr, NN);
    }
    // ---- layer 2 fused combine: allfeat = (f0 + f1 + A@f1) / 3 ----
    {
        int blocks = (NN * 32 + TPB - 1) / TPB;
        spmm_gather<true><<<blocks, TPB>>>(rs, ecv, f1, f1, 0x7FFFFFFF,
                                           allfeat, users_feature, items_feature, f1, NN);
    }

    // ---- bundle CSR build + gather: bund = Bi @ allfeat[NU:] ----
    hist_kernel<<<(nE_bi + TPB - 1) / TPB, TPB>>>(bi_rows, bdeg, nE_bi);
    scan_local<<<NBLK_BI, 256>>>(bdeg, brs, bbsums, NB);
    scan_bsums<<<1, 256>>>(bbsums, NBLK_BI);
    scan_add<<<(NB + TPB - 1) / TPB, TPB>>>(brs, bbsums, NB, nE_bi);
    csr_scatter<<<(nE_bi + TPB - 1) / TPB, TPB>>>(bi_rows, bi_cols, bi_vals,
                                                  brs, bcur, becv, nE_bi);
    {
        int blocks = (NB * 32 + TPB - 1) / TPB;
        spmm_gather<false><<<blocks, TPB>>>(brs, becv, allfeat + (size_t)NU * DD,
                                            allfeat + (size_t)NU * DD, 0x7FFFFFFF,
                                            bund, nullptr, nullptr, nullptr, NB);
    }

    // ---- BPR loss ----
    {
        int blocks = (BQ * 32 + TPB - 1) / TPB;
        bpr_loss_kernel<<<blocks, TPB>>>(users, bundles, allfeat, bund, out);
    }
}

// round 6
// speedup vs baseline: 1.6480x; 1.1156x over previous
#include <cuda_runtime.h>
#include <cuda_fp16.h>
#include <cstdint>

// Problem constants (from reference)
#define NU 100000
#define NI 50000
#define NB 20000
#define DD 64
#define NN (NU + NI)
#define BQ 4096
#define NE_PROP_MAX 4000000
#define NE_BI_MAX   600000

#define SCAN_ELEMS 1024   // elements per scan block (256 threads x 4)
#define NBLK_PROP ((NN + SCAN_ELEMS - 1) / SCAN_ELEMS)   // 147
#define NBLK_BI   ((NB + SCAN_ELEMS - 1) / SCAN_ELEMS)   // 20

// ---- scratch (static; no runtime allocation) ----
__device__ __half2 g_xh[(size_t)NN * DD / 2];   // concat features, half
__device__ __half2 g_f1h[(size_t)NN * DD / 2];  // layer-1 result, half
__device__ float   g_allfeat[(size_t)NN * DD];  // all_features fp32
__device__ float   g_bund[(size_t)NB * DD];     // bundle reps

// counters packed contiguously for one memset: [deg NN][cur NN][bdeg NB][bcur NB]
__device__ int    g_counts[2 * NN + 2 * NB];
__device__ int    g_rs[NN + 1];
__device__ int    g_brs[NB + 1];
__device__ int    g_bsums[NBLK_PROP];
__device__ int    g_bbsums[NBLK_BI];
__device__ float2 g_ecv[NE_PROP_MAX];
__device__ float2 g_becv[NE_BI_MAX];

// ---------------------------------------------------------------------------
// fp32 -> half2 conversion of the virtual concat [users ; items]
// ---------------------------------------------------------------------------
__global__ void to_half_kernel(const float* __restrict__ u, const float* __restrict__ it,
                               __half2* __restrict__ xh) {
    int i = blockIdx.x * blockDim.x + threadIdx.x;
    const int n_u = NU * DD / 2, n_tot = NN * DD / 2;
    if (i >= n_tot) return;
    float2 f = (i < n_u) ? reinterpret_cast<const float2*>(u)[i]
                         : reinterpret_cast<const float2*>(it)[i - n_u];
    xh[i] = __floats2half2_rn(f.x, f.y);
}

// ---------------------------------------------------------------------------
// combined degree histogram (prop then bi)
// ---------------------------------------------------------------------------
__global__ void hist_both(const int* __restrict__ prows, int* __restrict__ deg, int nEp,
                          const int* __restrict__ brows, int* __restrict__ bdeg, int nEb) {
    int e = blockIdx.x * blockDim.x + threadIdx.x;
    if (e < nEp) atomicAdd(&deg[prows[e]], 1);
    else if (e < nEp + nEb) atomicAdd(&bdeg[brows[e - nEp]], 1);
}

// ---------------------------------------------------------------------------
// exclusive scan, 3-phase, both arrays in one grid
// ---------------------------------------------------------------------------
__global__ void scan_local_both(const int* __restrict__ deg, int* __restrict__ excl,
                                int* __restrict__ bsums,
                                const int* __restrict__ bdeg, int* __restrict__ bexcl,
                                int* __restrict__ bbsums) {
    __shared__ int sh[256];
    int tid = threadIdx.x;
    const int* src; int* dst; int* bs; int n; int blk;
    if (blockIdx.x < NBLK_PROP) { src = deg;  dst = excl;  bs = bsums;  n = NN; blk = blockIdx.x; }
    else                        { src = bdeg; dst = bexcl; bs = bbsums; n = NB; blk = blockIdx.x - NBLK_PROP; }
    int base = blk * SCAN_ELEMS + tid * 4;
    int v[4]; int s = 0;
    #pragma unroll
    for (int k = 0; k < 4; k++) {
        v[k] = (base + k < n) ? src[base + k] : 0;
        s += v[k];
    }
    sh[tid] = s;
    __syncthreads();
    for (int off = 1; off < 256; off <<= 1) {
        int t = (tid >= off) ? sh[tid - off] : 0;
        __syncthreads();
        sh[tid] += t;
        __syncthreads();
    }
    if (tid == 255) bs[blk] = sh[255];
    int run = sh[tid] - s;
    #pragma unroll
    for (int k = 0; k < 4; k++) {
        if (base + k < n) dst[base + k] = run;
        run += v[k];
    }
}

__global__ void scan_bsums_both(int* __restrict__ bsums, int* __restrict__ bbsums) {
    __shared__ int sh[256];
    int tid = threadIdx.x;
    int* arr = (blockIdx.x == 0) ? bsums : bbsums;
    int nb   = (blockIdx.x == 0) ? NBLK_PROP : NBLK_BI;
    int v = (tid < nb) ? arr[tid] : 0;
    sh[tid] = v;
    __syncthreads();
    for (int off = 1; off < 256; off <<= 1) {
        int t = (tid >= off) ? sh[tid - off] : 0;
        __syncthreads();
        sh[tid] += t;
        __syncthreads();
    }
    if (tid < nb) arr[tid] = sh[tid] - v;
}

__global__ void scan_add_both(int* __restrict__ excl, const int* __restrict__ bsums, int totp,
                              int* __restrict__ bexcl, const int* __restrict__ bbsums, int totb) {
    int i = blockIdx.x * blockDim.x + threadIdx.x;
    if (i < NN) excl[i] += bsums[i / SCAN_ELEMS];
    else if (i < NN + NB) {
        int j = i - NN;
        bexcl[j] += bbsums[j / SCAN_ELEMS];
    }
    if (i == 0) { excl[NN] = totp; bexcl[NB] = totb; }
}

// ---------------------------------------------------------------------------
// combined CSR scatter-pack
// ---------------------------------------------------------------------------
__global__ void csr_scatter_both(const int* __restrict__ prows, const int* __restrict__ pcols,
                                 const float* __restrict__ pvals,
                                 const int* __restrict__ rs, int* __restrict__ cur,
                                 float2* __restrict__ ecv, int nEp,
                                 const int* __restrict__ brows, const int* __restrict__ bcols,
                                 const float* __restrict__ bvals,
                                 const int* __restrict__ brs, int* __restrict__ bcur,
                                 float2* __restrict__ becv, int nEb) {
    int e = blockIdx.x * blockDim.x + threadIdx.x;
    if (e < nEp) {
        int r = prows[e];
        int p = rs[r] + atomicAdd(&cur[r], 1);
        ecv[p] = make_float2(__int_as_float(pcols[e]), pvals[e]);
    } else if (e < nEp + nEb) {
        int i = e - nEp;
        int r = brows[i];
        int p = brs[r] + atomicAdd(&bcur[r], 1);
        becv[p] = make_float2(__int_as_float(bcols[i]), bvals[i]);
    }
}

// ---------------------------------------------------------------------------
// Half-precision gather SpMM: warp per row, lane owns 2 dims (half2).
// COMBINE (layer 2): out_f32[row] = (f0[row] + f1h[row] + acc) / 3,
// f0 = virtual fp32 concat [f0u ; f0i]. Else: write half2 to out_h.
// ---------------------------------------------------------------------------
template<bool COMBINE>
__global__ void spmm_gather_h(const int* __restrict__ rs, const float2* __restrict__ ecv,
                              const __half2* __restrict__ x,
                              __half2* __restrict__ out_h,
                              float* __restrict__ out_f,
                              const float* __restrict__ f0u, const float* __restrict__ f0i,
                              int nrows) {
    int w = (blockIdx.x * blockDim.x + threadIdx.x) >> 5;
    int lane = threadIdx.x & 31;
    if (w >= nrows) return;

    int s = rs[w];
    int e = rs[w + 1];
    float accx = 0.f, accy = 0.f;

    for (int base = s; base < e; base += 32) {
        int idx = base + lane;
        float2 cv = make_float2(__int_as_float(0), 0.f);
        if (idx < e) cv = ecv[idx];
        int cnt = min(32, e - base);
        #pragma unroll 4
        for (int j = 0; j < cnt; ++j) {
            int c   = __shfl_sync(0xFFFFFFFFu, __float_as_int(cv.x), j);
            float v = __shfl_sync(0xFFFFFFFFu, cv.y, j);
            __half2 xv = x[(size_t)c * (DD / 2) + lane];
            float2 xf = __half22float2(xv);
            accx = fmaf(v, xf.x, accx);
            accy = fmaf(v, xf.y, accy);
        }
    }

    if (COMBINE) {
        const float* f0 = (w < NU) ? (f0u + (size_t)w * DD)
                                   : (f0i + (size_t)(w - NU) * DD);
        float2 a = reinterpret_cast<const float2*>(f0)[lane];
        float2 b = __half22float2(x[(size_t)w * (DD / 2) + lane]);  // x == f1h here
        accx = (accx + a.x + b.x) * (1.0f / 3.0f);
        accy = (accy + a.y + b.y) * (1.0f / 3.0f);
        reinterpret_cast<float2*>(out_f + (size_t)w * DD)[lane] = make_float2(accx, accy);
    } else {
        out_h[(size_t)w * (DD / 2) + lane] = __floats2half2_rn(accx, accy);
    }
}

// ---------------------------------------------------------------------------
// fp32 gather SpMM (bundle aggregation; small, precision-safe)
// ---------------------------------------------------------------------------
__global__ void spmm_gather_f(const int* __restrict__ rs, const float2* __restrict__ ecv,
                              const float* __restrict__ x, float* __restrict__ out, int nrows) {
    int w = (blockIdx.x * blockDim.x + threadIdx.x) >> 5;
    int lane = threadIdx.x & 31;
    if (w >= nrows) return;

    int s = rs[w];
    int e = rs[w + 1];
    float accx = 0.f, accy = 0.f;

    for (int base = s; base < e; base += 32) {
        int idx = base + lane;
        float2 cv = make_float2(__int_as_float(0), 0.f);
        if (idx < e) cv = ecv[idx];
        int cnt = min(32, e - base);
        #pragma unroll 4
        for (int j = 0; j < cnt; ++j) {
            int c   = __shfl_sync(0xFFFFFFFFu, __float_as_int(cv.x), j);
            float v = __shfl_sync(0xFFFFFFFFu, cv.y, j);
            float2 xv = reinterpret_cast<const float2*>(x + (size_t)c * DD)[lane];
            accx = fmaf(v, xv.x, accx);
            accy = fmaf(v, xv.y, accy);
        }
    }
    reinterpret_cast<float2*>(out + (size_t)w * DD)[lane] = make_float2(accx, accy);
}

// ---------------------------------------------------------------------------
// BPR loss: one warp per query row.
// ---------------------------------------------------------------------------
__global__ void bpr_loss_kernel(const int* __restrict__ users,
                                const int* __restrict__ bundles,
                                const float* __restrict__ feat,
                                const float* __restrict__ bund,
                                float* __restrict__ out) {
    int w = (blockIdx.x * blockDim.x + threadIdx.x) >> 5;
    int lane = threadIdx.x & 31;
    if (w >= BQ) return;

    int u  = users[w];
    int b0 = bundles[2 * w + 0];
    int b1 = bundles[2 * w + 1];

    float2 ue = reinterpret_cast<const float2*>(feat + (size_t)u  * DD)[lane];
    float2 e0 = reinterpret_cast<const float2*>(bund + (size_t)b0 * DD)[lane];
    float2 e1 = reinterpret_cast<const float2*>(bund + (size_t)b1 * DD)[lane];

    float d = ue.x * (e0.x - e1.x) + ue.y * (e0.y - e1.y);
    #pragma unroll
    for (int o = 16; o > 0; o >>= 1)
        d += __shfl_xor_sync(0xFFFFFFFFu, d, o);

    if (lane == 0) {
        float x = d;
        float sp = (x > 0.0f) ? log1pf(expf(-x)) : (-x + log1pf(expf(x)));
        atomicAdd(out, sp * (1.0f / BQ));
    }
}

// ---------------------------------------------------------------------------
// Launch
// ---------------------------------------------------------------------------
extern "C" void kernel_launch(void* const* d_in, const int* in_sizes, int n_in,
                              void* d_out, int out_size) {
    const float* users_feature = (const float*)d_in[0];
    const float* items_feature = (const float*)d_in[1];
    const float* prop_vals     = (const float*)d_in[2];
    const float* bi_vals       = (const float*)d_in[3];
    const int*   prop_rows     = (const int*)d_in[4];
    const int*   prop_cols     = (const int*)d_in[5];
    const int*   bi_rows       = (const int*)d_in[6];
    const int*   bi_cols       = (const int*)d_in[7];
    const int*   users         = (const int*)d_in[8];
    const int*   bundles       = (const int*)d_in[9];
    float*       out           = (float*)d_out;

    int nE_prop = in_sizes[4];   // 4,000,000
    int nE_bi   = in_sizes[6];   // 600,000

    __half2 *xh, *f1h;
    float *allfeat, *bund;
    int *counts, *rs, *brs, *bsums, *bbsums;
    float2 *ecv, *becv;
    cudaGetSymbolAddress((void**)&xh,      g_xh);
    cudaGetSymbolAddress((void**)&f1h,     g_f1h);
    cudaGetSymbolAddress((void**)&allfeat, g_allfeat);
    cudaGetSymbolAddress((void**)&bund,    g_bund);
    cudaGetSymbolAddress((void**)&counts,  g_counts);
    cudaGetSymbolAddress((void**)&rs,      g_rs);
    cudaGetSymbolAddress((void**)&brs,     g_brs);
    cudaGetSymbolAddress((void**)&bsums,   g_bsums);
    cudaGetSymbolAddress((void**)&bbsums,  g_bbsums);
    cudaGetSymbolAddress((void**)&ecv,     g_ecv);
    cudaGetSymbolAddress((void**)&becv,    g_becv);

    int* deg  = counts;
    int* cur  = counts + NN;
    int* bdeg = counts + 2 * NN;
    int* bcur = counts + 2 * NN + NB;

    const int TPB = 256;

    cudaMemsetAsync(counts, 0, (2 * NN + 2 * NB) * sizeof(int), 0);
    cudaMemsetAsync(d_out,  0, (size_t)out_size * sizeof(float), 0);

    // ---- feature -> half conversion ----
    {
        int n = NN * DD / 2;
        to_half_kernel<<<(n + TPB - 1) / TPB, TPB>>>(users_feature, items_feature, xh);
    }

    // ---- combined CSR builds ----
    {
        int nE = nE_prop + nE_bi;
        hist_both<<<(nE + TPB - 1) / TPB, TPB>>>(prop_rows, deg, nE_prop, bi_rows, bdeg, nE_bi);
        scan_local_both<<<NBLK_PROP + NBLK_BI, 256>>>(deg, rs, bsums, bdeg, brs, bbsums);
        scan_bsums_both<<<2, 256>>>(bsums, bbsums);
        scan_add_both<<<(NN + NB + TPB - 1) / TPB, TPB>>>(rs, bsums, nE_prop, brs, bbsums, nE_bi);
        csr_scatter_both<<<(nE + TPB - 1) / TPB, TPB>>>(prop_rows, prop_cols, prop_vals,
                                                        rs, cur, ecv, nE_prop,
                                                        bi_rows, bi_cols, bi_vals,
                                                        brs, bcur, becv, nE_bi);
    }

    // ---- layer 1 (half gather): f1h = A @ xh ----
    {
        int blocks = (NN * 32 + TPB - 1) / TPB;
        spmm_gather_h<false><<<blocks, TPB>>>(rs, ecv, xh, f1h, nullptr,
                                              nullptr, nullptr, NN);
    }
    // ---- layer 2 fused combine: allfeat = (f0 + f1 + A@f1) / 3 ----
    {
        int blocks = (NN * 32 + TPB - 1) / TPB;
        spmm_gather_h<true><<<blocks, TPB>>>(rs, ecv, f1h, nullptr, allfeat,
                                             users_feature, items_feature, NN);
    }
    // ---- bundle aggregation (fp32): bund = Bi @ allfeat[NU:] ----
    {
        int blocks = (NB * 32 + TPB - 1) / TPB;
        spmm_gather_f<<<blocks, TPB>>>(brs, becv, allfeat + (size_t)NU * DD, bund, NB);
    }
    // ---- BPR loss ----
    {
        int blocks = (BQ * 32 + TPB - 1) / TPB;
        bpr_loss_kernel<<<blocks, TPB>>>(users, bundles, allfeat, bund, out);
    }
}

// round 8
// speedup vs baseline: 1.6853x; 1.0226x over previous
#include <cuda_runtime.h>
#include <cuda_fp16.h>
#include <cstdint>

// Problem constants (from reference)
#define NU 100000
#define NI 50000
#define NB 20000
#define DD 64
#define NN (NU + NI)
#define BQ 4096
#define NE_PROP_MAX 4000000
#define NE_BI_MAX   600000

#define SCAN_ELEMS 1024   // elements per scan block (256 threads x 4)
#define NBLK_PROP ((NN + SCAN_ELEMS - 1) / SCAN_ELEMS)   // 147
#define NBLK_BI   ((NB + SCAN_ELEMS - 1) / SCAN_ELEMS)   // 20

// ---- scratch (static; no runtime allocation) ----
__device__ __half2 g_xh[(size_t)NN * DD / 2];   // concat features, half
__device__ __half2 g_f1h[(size_t)NN * DD / 2];  // layer-1 result, half
__device__ float   g_allfeat[(size_t)NN * DD];  // all_features fp32
__device__ float   g_bund[(size_t)NB * DD];     // bundle reps

// counters packed contiguously for one memset: [deg NN][cur NN][bdeg NB][bcur NB]
__device__ int    g_counts[2 * NN + 2 * NB];
__device__ int    g_rs[NN + 1];
__device__ int    g_brs[NB + 1];
__device__ int    g_bsums[NBLK_PROP];
__device__ int    g_bbsums[NBLK_BI];
__device__ float2 g_ecv[NE_PROP_MAX];
__device__ float2 g_becv[NE_BI_MAX];

// ---------------------------------------------------------------------------
// fp32 -> half2 conversion of the virtual concat [users ; items]
// ---------------------------------------------------------------------------
__global__ void to_half_kernel(const float* __restrict__ u, const float* __restrict__ it,
                               __half2* __restrict__ xh) {
    int i = blockIdx.x * blockDim.x + threadIdx.x;
    const int n_u = NU * DD / 2, n_tot = NN * DD / 2;
    if (i >= n_tot) return;
    float2 f = (i < n_u) ? reinterpret_cast<const float2*>(u)[i]
                         : reinterpret_cast<const float2*>(it)[i - n_u];
    xh[i] = __floats2half2_rn(f.x, f.y);
}

// ---------------------------------------------------------------------------
// combined degree histogram (prop then bi)
// ---------------------------------------------------------------------------
__global__ void hist_both(const int* __restrict__ prows, int* __restrict__ deg, int nEp,
                          const int* __restrict__ brows, int* __restrict__ bdeg, int nEb) {
    int e = blockIdx.x * blockDim.x + threadIdx.x;
    if (e < nEp) atomicAdd(&deg[prows[e]], 1);
    else if (e < nEp + nEb) atomicAdd(&bdeg[brows[e - nEp]], 1);
}

// ---------------------------------------------------------------------------
// exclusive scan, 3-phase, both arrays in one grid
// ---------------------------------------------------------------------------
__global__ void scan_local_both(const int* __restrict__ deg, int* __restrict__ excl,
                                int* __restrict__ bsums,
                                const int* __restrict__ bdeg, int* __restrict__ bexcl,
                                int* __restrict__ bbsums) {
    __shared__ int sh[256];
    int tid = threadIdx.x;
    const int* src; int* dst; int* bs; int n; int blk;
    if (blockIdx.x < NBLK_PROP) { src = deg;  dst = excl;  bs = bsums;  n = NN; blk = blockIdx.x; }
    else                        { src = bdeg; dst = bexcl; bs = bbsums; n = NB; blk = blockIdx.x - NBLK_PROP; }
    int base = blk * SCAN_ELEMS + tid * 4;
    int v[4]; int s = 0;
    #pragma unroll
    for (int k = 0; k < 4; k++) {
        v[k] = (base + k < n) ? src[base + k] : 0;
        s += v[k];
    }
    sh[tid] = s;
    __syncthreads();
    for (int off = 1; off < 256; off <<= 1) {
        int t = (tid >= off) ? sh[tid - off] : 0;
        __syncthreads();
        sh[tid] += t;
        __syncthreads();
    }
    if (tid == 255) bs[blk] = sh[255];
    int run = sh[tid] - s;
    #pragma unroll
    for (int k = 0; k < 4; k++) {
        if (base + k < n) dst[base + k] = run;
        run += v[k];
    }
}

__global__ void scan_bsums_both(int* __restrict__ bsums, int* __restrict__ bbsums) {
    __shared__ int sh[256];
    int tid = threadIdx.x;
    int* arr = (blockIdx.x == 0) ? bsums : bbsums;
    int nb   = (blockIdx.x == 0) ? NBLK_PROP : NBLK_BI;
    int v = (tid < nb) ? arr[tid] : 0;
    sh[tid] = v;
    __syncthreads();
    for (int off = 1; off < 256; off <<= 1) {
        int t = (tid >= off) ? sh[tid - off] : 0;
        __syncthreads();
        sh[tid] += t;
        __syncthreads();
    }
    if (tid < nb) arr[tid] = sh[tid] - v;
}

__global__ void scan_add_both(int* __restrict__ excl, const int* __restrict__ bsums, int totp,
                              int* __restrict__ bexcl, const int* __restrict__ bbsums, int totb) {
    int i = blockIdx.x * blockDim.x + threadIdx.x;
    if (i < NN) excl[i] += bsums[i / SCAN_ELEMS];
    else if (i < NN + NB) {
        int j = i - NN;
        bexcl[j] += bbsums[j / SCAN_ELEMS];
    }
    if (i == 0) { excl[NN] = totp; bexcl[NB] = totb; }
}

// ---------------------------------------------------------------------------
// combined CSR scatter-pack
// ---------------------------------------------------------------------------
__global__ void csr_scatter_both(const int* __restrict__ prows, const int* __restrict__ pcols,
                                 const float* __restrict__ pvals,
                                 const int* __restrict__ rs, int* __restrict__ cur,
                                 float2* __restrict__ ecv, int nEp,
                                 const int* __restrict__ brows, const int* __restrict__ bcols,
                                 const float* __restrict__ bvals,
                                 const int* __restrict__ brs, int* __restrict__ bcur,
                                 float2* __restrict__ becv, int nEb) {
    int e = blockIdx.x * blockDim.x + threadIdx.x;
    if (e < nEp) {
        int r = prows[e];
        int p = rs[r] + atomicAdd(&cur[r], 1);
        ecv[p] = make_float2(__int_as_float(pcols[e]), pvals[e]);
    } else if (e < nEp + nEb) {
        int i = e - nEp;
        int r = brows[i];
        int p = brs[r] + atomicAdd(&bcur[r], 1);
        becv[p] = make_float2(__int_as_float(bcols[i]), bvals[i]);
    }
}

// ---------------------------------------------------------------------------
// Half-precision gather SpMM, no-shuffle version: warp per row, lane owns
// 2 dims (half2). Edge records read uniformly per warp (HW broadcast),
// 4-edge manual unroll for MLP, dual accumulators.
// COMBINE (layer 2): out_f32[row] = (f0[row] + f1h[row] + acc) / 3.
// ---------------------------------------------------------------------------
template<bool COMBINE>
__global__ void spmm_gather_h(const int* __restrict__ rs, const float2* __restrict__ ecv,
                              const __half2* __restrict__ x,
                              __half2* __restrict__ out_h,
                              float* __restrict__ out_f,
                              const float* __restrict__ f0u, const float* __restrict__ f0i,
                              int nrows) {
    int w = (blockIdx.x * blockDim.x + threadIdx.x) >> 5;
    int lane = threadIdx.x & 31;
    if (w >= nrows) return;

    int s = rs[w];
    int e = rs[w + 1];
    float a0x = 0.f, a0y = 0.f, a1x = 0.f, a1y = 0.f;

    int j = s;
    for (; j + 4 <= e; j += 4) {
        float2 c0 = __ldg(&ecv[j + 0]);
        float2 c1 = __ldg(&ecv[j + 1]);
        float2 c2 = __ldg(&ecv[j + 2]);
        float2 c3 = __ldg(&ecv[j + 3]);
        __half2 h0 = x[(size_t)__float_as_int(c0.x) * (DD / 2) + lane];
        __half2 h1 = x[(size_t)__float_as_int(c1.x) * (DD / 2) + lane];
        __half2 h2 = x[(size_t)__float_as_int(c2.x) * (DD / 2) + lane];
        __half2 h3 = x[(size_t)__float_as_int(c3.x) * (DD / 2) + lane];
        float2 f0 = __half22float2(h0);
        float2 f1 = __half22float2(h1);
        float2 f2 = __half22float2(h2);
        float2 f3 = __half22float2(h3);
        a0x = fmaf(c0.y, f0.x, a0x); a0y = fmaf(c0.y, f0.y, a0y);
        a1x = fmaf(c1.y, f1.x, a1x); a1y = fmaf(c1.y, f1.y, a1y);
        a0x = fmaf(c2.y, f2.x, a0x); a0y = fmaf(c2.y, f2.y, a0y);
        a1x = fmaf(c3.y, f3.x, a1x); a1y = fmaf(c3.y, f3.y, a1y);
    }
    for (; j < e; ++j) {
        float2 c0 = __ldg(&ecv[j]);
        float2 f0 = __half22float2(x[(size_t)__float_as_int(c0.x) * (DD / 2) + lane]);
        a0x = fmaf(c0.y, f0.x, a0x); a0y = fmaf(c0.y, f0.y, a0y);
    }
    float accx = a0x + a1x, accy = a0y + a1y;

    if (COMBINE) {
        const float* f0 = (w < NU) ? (f0u + (size_t)w * DD)
                                   : (f0i + (size_t)(w - NU) * DD);
        float2 a = reinterpret_cast<const float2*>(f0)[lane];
        float2 b = __half22float2(x[(size_t)w * (DD / 2) + lane]);  // x == f1h here
        accx = (accx + a.x + b.x) * (1.0f / 3.0f);
        accy = (accy + a.y + b.y) * (1.0f / 3.0f);
        reinterpret_cast<float2*>(out_f + (size_t)w * DD)[lane] = make_float2(accx, accy);
    } else {
        out_h[(size_t)w * (DD / 2) + lane] = __floats2half2_rn(accx, accy);
    }
}

// ---------------------------------------------------------------------------
// fp32 gather SpMM (bundle aggregation), same no-shuffle structure
// ---------------------------------------------------------------------------
__global__ void spmm_gather_f(const int* __restrict__ rs, const float2* __restrict__ ecv,
                              const float* __restrict__ x, float* __restrict__ out, int nrows) {
    int w = (blockIdx.x * blockDim.x + threadIdx.x) >> 5;
    int lane = threadIdx.x & 31;
    if (w >= nrows) return;

    int s = rs[w];
    int e = rs[w + 1];
    float a0x = 0.f, a0y = 0.f, a1x = 0.f, a1y = 0.f;

    int j = s;
    for (; j + 4 <= e; j += 4) {
        float2 c0 = __ldg(&ecv[j + 0]);
        float2 c1 = __ldg(&ecv[j + 1]);
        float2 c2 = __ldg(&ecv[j + 2]);
        float2 c3 = __ldg(&ecv[j + 3]);
        float2 f0 = reinterpret_cast<const float2*>(x + (size_t)__float_as_int(c0.x) * DD)[lane];
        float2 f1 = reinterpret_cast<const float2*>(x + (size_t)__float_as_int(c1.x) * DD)[lane];
        float2 f2 = reinterpret_cast<const float2*>(x + (size_t)__float_as_int(c2.x) * DD)[lane];
        float2 f3 = reinterpret_cast<const float2*>(x + (size_t)__float_as_int(c3.x) * DD)[lane];
        a0x = fmaf(c0.y, f0.x, a0x); a0y = fmaf(c0.y, f0.y, a0y);
        a1x = fmaf(c1.y, f1.x, a1x); a1y = fmaf(c1.y, f1.y, a1y);
        a0x = fmaf(c2.y, f2.x, a0x); a0y = fmaf(c2.y, f2.y, a0y);
        a1x = fmaf(c3.y, f3.x, a1x); a1y = fmaf(c3.y, f3.y, a1y);
    }
    for (; j < e; ++j) {
        float2 c0 = __ldg(&ecv[j]);
        float2 f0 = reinterpret_cast<const float2*>(x + (size_t)__float_as_int(c0.x) * DD)[lane];
        a0x = fmaf(c0.y, f0.x, a0x); a0y = fmaf(c0.y, f0.y, a0y);
    }
    reinterpret_cast<float2*>(out + (size_t)w * DD)[lane] = make_float2(a0x + a1x, a0y + a1y);
}

// ---------------------------------------------------------------------------
// BPR loss: one warp per query row.
// ---------------------------------------------------------------------------
__global__ void bpr_loss_kernel(const int* __restrict__ users,
                                const int* __restrict__ bundles,
                                const float* __restrict__ feat,
                                const float* __restrict__ bund,
                                float* __restrict__ out) {
    int w = (blockIdx.x * blockDim.x + threadIdx.x) >> 5;
    int lane = threadIdx.x & 31;
    if (w >= BQ) return;

    int u  = users[w];
    int b0 = bundles[2 * w + 0];
    int b1 = bundles[2 * w + 1];

    float2 ue = reinterpret_cast<const float2*>(feat + (size_t)u  * DD)[lane];
    float2 e0 = reinterpret_cast<const float2*>(bund + (size_t)b0 * DD)[lane];
    float2 e1 = reinterpret_cast<const float2*>(bund + (size_t)b1 * DD)[lane];

    float d = ue.x * (e0.x - e1.x) + ue.y * (e0.y - e1.y);
    #pragma unroll
    for (int o = 16; o > 0; o >>= 1)
        d += __shfl_xor_sync(0xFFFFFFFFu, d, o);

    if (lane == 0) {
        float x = d;
        float sp = (x > 0.0f) ? log1pf(expf(-x)) : (-x + log1pf(expf(x)));
        atomicAdd(out, sp * (1.0f / BQ));
    }
}

// ---------------------------------------------------------------------------
// Launch
// ---------------------------------------------------------------------------
extern "C" void kernel_launch(void* const* d_in, const int* in_sizes, int n_in,
                              void* d_out, int out_size) {
    const float* users_feature = (const float*)d_in[0];
    const float* items_feature = (const float*)d_in[1];
    const float* prop_vals     = (const float*)d_in[2];
    const float* bi_vals       = (const float*)d_in[3];
    const int*   prop_rows     = (const int*)d_in[4];
    const int*   prop_cols     = (const int*)d_in[5];
    const int*   bi_rows       = (const int*)d_in[6];
    const int*   bi_cols       = (const int*)d_in[7];
    const int*   users         = (const int*)d_in[8];
    const int*   bundles       = (const int*)d_in[9];
    float*       out           = (float*)d_out;

    int nE_prop = in_sizes[4];   // 4,000,000
    int nE_bi   = in_sizes[6];   // 600,000

    __half2 *xh, *f1h;
    float *allfeat, *bund;
    int *counts, *rs, *brs, *bsums, *bbsums;
    float2 *ecv, *becv;
    cudaGetSymbolAddress((void**)&xh,      g_xh);
    cudaGetSymbolAddress((void**)&f1h,     g_f1h);
    cudaGetSymbolAddress((void**)&allfeat, g_allfeat);
    cudaGetSymbolAddress((void**)&bund,    g_bund);
    cudaGetSymbolAddress((void**)&counts,  g_counts);
    cudaGetSymbolAddress((void**)&rs,      g_rs);
    cudaGetSymbolAddress((void**)&brs,     g_brs);
    cudaGetSymbolAddress((void**)&bsums,   g_bsums);
    cudaGetSymbolAddress((void**)&bbsums,  g_bbsums);
    cudaGetSymbolAddress((void**)&ecv,     g_ecv);
    cudaGetSymbolAddress((void**)&becv,    g_becv);

    int* deg  = counts;
    int* cur  = counts + NN;
    int* bdeg = counts + 2 * NN;
    int* bcur = counts + 2 * NN + NB;

    const int TPB = 256;

    cudaMemsetAsync(counts, 0, (2 * NN + 2 * NB) * sizeof(int), 0);
    cudaMemsetAsync(d_out,  0, (size_t)out_size * sizeof(float), 0);

    // ---- feature -> half conversion ----
    {
        int n = NN * DD / 2;
        to_half_kernel<<<(n + TPB - 1) / TPB, TPB>>>(users_feature, items_feature, xh);
    }

    // ---- combined CSR builds ----
    {
        int nE = nE_prop + nE_bi;
        hist_both<<<(nE + TPB - 1) / TPB, TPB>>>(prop_rows, deg, nE_prop, bi_rows, bdeg, nE_bi);
        scan_local_both<<<NBLK_PROP + NBLK_BI, 256>>>(deg, rs, bsums, bdeg, brs, bbsums);
        scan_bsums_both<<<2, 256>>>(bsums, bbsums);
        scan_add_both<<<(NN + NB + TPB - 1) / TPB, TPB>>>(rs, bsums, nE_prop, brs, bbsums, nE_bi);
        csr_scatter_both<<<(nE + TPB - 1) / TPB, TPB>>>(prop_rows, prop_cols, prop_vals,
                                                        rs, cur, ecv, nE_prop,
                                                        bi_rows, bi_cols, bi_vals,
                                                        brs, bcur, becv, nE_bi);
    }

    // ---- layer 1 (half gather): f1h = A @ xh ----
    {
        int blocks = (NN * 32 + TPB - 1) / TPB;
        spmm_gather_h<false><<<blocks, TPB>>>(rs, ecv, xh, f1h, nullptr,
                                              nullptr, nullptr, NN);
    }
    // ---- layer 2 fused combine: allfeat = (f0 + f1 + A@f1) / 3 ----
    {
        int blocks = (NN * 32 + TPB - 1) / TPB;
        spmm_gather_h<true><<<blocks, TPB>>>(rs, ecv, f1h, nullptr, allfeat,
                                             users_feature, items_feature, NN);
    }
    // ---- bundle aggregation (fp32): bund = Bi @ allfeat[NU:] ----
    {
        int blocks = (NB * 32 + TPB - 1) / TPB;
        spmm_gather_f<<<blocks, TPB>>>(brs, becv, allfeat + (size_t)NU * DD, bund, NB);
    }
    // ---- BPR loss ----
    {
        int blocks = (BQ * 32 + TPB - 1) / TPB;
        bpr_loss_kernel<<<blocks, TPB>>>(users, bundles, allfeat, bund, out);
    }
}